// round 8
// baseline (speedup 1.0000x reference)
#include <cuda_runtime.h>
#include <cuda_bf16.h>
#include <stdint.h>

// Problem dims
#define S_LEN 512
#define BATCH 64
#define DIM   1024
#define HID   1024
#define NG    4096
#define NBLK  128    // persistent recurrence blocks

#define A_ST  1032   // Wh smem row stride (bf16)
#define B_ST  136    // h-chunk smem row stride (bf16)

// recurrence smem layout (bytes)
#define OFF_AL  66048           // 32*A_ST*2
#define OFF_B0H 132096
#define OFF_B0L 149504
#define OFF_B1H 166912
#define OFF_B1L 184320
#define SMEM_REC 201728
#define GBS 68                  // gbuf row stride (floats); 256 rows overlay both B buffers

// xproj smem: 2 buffers x 20480 bf16 (Ah 0 / Al 5120 / Bh 10240 / Bl 15360), stride 40
#define XA_ST 40
#define XBUF_ELEMS 20480
#define SMEM_XP (2 * XBUF_ELEMS * 2)

// ---------------- device global scratch ----------------
__device__ __nv_bfloat16 g_in_hi[(size_t)BATCH * S_LEN * DIM];
__device__ __nv_bfloat16 g_in_lo[(size_t)BATCH * S_LEN * DIM];
__device__ __nv_bfloat16 g_wx_hi[(size_t)NG * DIM];
__device__ __nv_bfloat16 g_wx_lo[(size_t)NG * DIM];
__device__ __nv_bfloat16 g_wh_hi[(size_t)NG * HID];
__device__ __nv_bfloat16 g_wh_lo[(size_t)NG * HID];
__device__ float         g_xp[(size_t)S_LEN * NG * BATCH];   // [s][n][b]
__device__ float         g_c[BATCH * HID];
__device__ __nv_bfloat16 g_h_hi[2][BATCH * HID];
__device__ __nv_bfloat16 g_h_lo[2][BATCH * HID];
__device__ unsigned      g_flags[NBLK];                      // flag-array grid barrier

// ---------------- helpers ----------------
__device__ __forceinline__ void mma16816(float* c, const uint32_t* a, const uint32_t* b) {
    asm volatile(
        "mma.sync.aligned.m16n8k16.row.col.f32.bf16.bf16.f32 "
        "{%0,%1,%2,%3}, {%4,%5,%6,%7}, {%8,%9}, {%0,%1,%2,%3};\n"
        : "+f"(c[0]), "+f"(c[1]), "+f"(c[2]), "+f"(c[3])
        : "r"(a[0]), "r"(a[1]), "r"(a[2]), "r"(a[3]), "r"(b[0]), "r"(b[1]));
}
__device__ __forceinline__ void ldsm4(uint32_t* r, const void* p) {
    uint32_t addr = (uint32_t)__cvta_generic_to_shared(p);
    asm volatile("ldmatrix.sync.aligned.m8n8.x4.shared.b16 {%0,%1,%2,%3}, [%4];"
                 : "=r"(r[0]), "=r"(r[1]), "=r"(r[2]), "=r"(r[3]) : "r"(addr));
}
__device__ __forceinline__ uint32_t smem_u32(const void* p) {
    return (uint32_t)__cvta_generic_to_shared(p);
}
#define CPA(dst, src) asm volatile("cp.async.cg.shared.global [%0], [%1], 16;\n" :: "r"(dst), "l"(src))
#define CP_COMMIT()   asm volatile("cp.async.commit_group;\n")
#define CP_WAIT(n)    asm volatile("cp.async.wait_group %0;\n" :: "n"(n))

__global__ void split_kernel(const float* __restrict__ src,
                             __nv_bfloat16* __restrict__ hi,
                             __nv_bfloat16* __restrict__ lo, size_t n) {
    size_t i = (size_t)blockIdx.x * blockDim.x + threadIdx.x;
    if (i < n) {
        float v = src[i];
        __nv_bfloat16 h = __float2bfloat16_rn(v);
        hi[i] = h;
        lo[i] = __float2bfloat16_rn(v - __bfloat162float(h));
    }
}

__global__ void init_kernel() {
    int i = blockIdx.x * blockDim.x + threadIdx.x;
    if (i < NBLK) g_flags[i] = 0u;
    if (i < BATCH * HID) {
        __nv_bfloat16 z = __float2bfloat16_rn(0.f);
        g_h_hi[0][i] = z; g_h_lo[0][i] = z;
        g_h_hi[1][i] = z; g_h_lo[1][i] = z;
    }
}

// ---------------- x-projection GEMM (validated R3) ----------------
__global__ void __launch_bounds__(256, 2) xproj_kernel() {
    extern __shared__ __align__(16) __nv_bfloat16 xs[];
    const int s0 = blockIdx.y * 2;
    const int n0 = blockIdx.x * 128;
    const int t  = threadIdx.x;
    const int w  = t >> 5, l = t & 31;
    const int wm = (w & 3) * 32;
    const int wc = (w >> 2) * 64;

    float acc[2][8][4];
#pragma unroll
    for (int i = 0; i < 2; i++)
#pragma unroll
        for (int j = 0; j < 8; j++)
#pragma unroll
            for (int k = 0; k < 4; k++) acc[i][j][k] = 0.f;

    const int lr  = t >> 2;
    const int lcq = (t & 3) * 8;
    const int qr = l >> 2, tg = l & 3;
    const int a_col = (l >> 4) * 8;
    const int b_col = ((l >> 3) & 1) * 8;

    auto stage = [&](int k0, int bs) {
        __nv_bfloat16* base = xs + bs * XBUF_ELEMS;
#pragma unroll
        for (int j = 0; j < 2; j++) {
            int r = lr + j * 64;
            size_t ga = (size_t)(n0 + r) * DIM + k0 + lcq;
            CPA(smem_u32(base + r * XA_ST + lcq),        g_wx_hi + ga);
            CPA(smem_u32(base + 5120 + r * XA_ST + lcq), g_wx_lo + ga);
            int b = r & 63, sl = r >> 6;
            size_t gb = ((size_t)b * S_LEN + s0 + sl) * DIM + k0 + lcq;
            CPA(smem_u32(base + 10240 + r * XA_ST + lcq), g_in_hi + gb);
            CPA(smem_u32(base + 15360 + r * XA_ST + lcq), g_in_lo + gb);
        }
    };

    stage(0, 0);
    CP_COMMIT();

    const int NCH = DIM / 32;
    for (int c = 0; c < NCH; c++) {
        if (c + 1 < NCH) {
            stage((c + 1) * 32, (c + 1) & 1);
            CP_COMMIT();
            CP_WAIT(1);
        } else {
            CP_WAIT(0);
        }
        __syncthreads();
        const __nv_bfloat16* base = xs + (c & 1) * XBUF_ELEMS;
#pragma unroll
        for (int kk = 0; kk < 32; kk += 16) {
            uint32_t ah[2][4], al[2][4];
#pragma unroll
            for (int mt = 0; mt < 2; mt++) {
                int a_row = wm + mt * 16 + (l & 15);
                ldsm4(ah[mt], base + a_row * XA_ST + kk + a_col);
                ldsm4(al[mt], base + 5120 + a_row * XA_ST + kk + a_col);
            }
#pragma unroll
            for (int bg = 0; bg < 4; bg++) {
                int b_row = wc + bg * 16 + (l & 7) + ((l >> 4) << 3);
                uint32_t bh[4], bl[4];
                ldsm4(bh, base + 10240 + b_row * XA_ST + kk + b_col);
                ldsm4(bl, base + 15360 + b_row * XA_ST + kk + b_col);
                float* a00 = acc[0][2 * bg];
                float* a01 = acc[0][2 * bg + 1];
                float* a10 = acc[1][2 * bg];
                float* a11 = acc[1][2 * bg + 1];
                mma16816(a00, ah[0], &bh[0]); mma16816(a10, ah[1], &bh[0]);
                mma16816(a01, ah[0], &bh[2]); mma16816(a11, ah[1], &bh[2]);
                mma16816(a00, ah[0], &bl[0]); mma16816(a10, ah[1], &bl[0]);
                mma16816(a01, ah[0], &bl[2]); mma16816(a11, ah[1], &bl[2]);
                mma16816(a00, al[0], &bh[0]); mma16816(a10, al[1], &bh[0]);
                mma16816(a01, al[0], &bh[2]); mma16816(a11, al[1], &bh[2]);
            }
        }
        __syncthreads();
    }

#pragma unroll
    for (int mt = 0; mt < 2; mt++) {
#pragma unroll
        for (int bg = 0; bg < 4; bg++) {
#pragma unroll
            for (int half = 0; half < 2; half++) {
                const float* a = acc[mt][2 * bg + half];
                int n = n0 + wm + mt * 16 + qr;
                int cc = wc + bg * 16 + half * 8 + tg * 2;
                int s = s0 + (cc >> 6);
                int b = cc & 63;
                size_t base = ((size_t)s * NG + n) * BATCH + b;
                *(float2*)&g_xp[base]             = make_float2(a[0], a[1]);
                *(float2*)&g_xp[base + 8 * BATCH] = make_float2(a[2], a[3]);
            }
        }
    }
}

// ---------------- persistent recurrence kernel (32m x 64n warp tiles, K-split 8) ----------------
// 128 blocks x 256 threads. Block: 32 gate rows (4 gates x 8 h) x 64 batch.
// Warp q (=w) covers K-slice [q*16, q*16+16) of each 128-K chunk, full 32x64 C tile.
__global__ void __launch_bounds__(256) lstm_rec_kernel(const float* __restrict__ bias,
                                                       float* __restrict__ out) {
    extern __shared__ __align__(16) char smem[];
    __nv_bfloat16* Ah = (__nv_bfloat16*)(smem);
    __nv_bfloat16* Al = (__nv_bfloat16*)(smem + OFF_AL);
    __nv_bfloat16* BufH[2] = { (__nv_bfloat16*)(smem + OFF_B0H), (__nv_bfloat16*)(smem + OFF_B1H) };
    __nv_bfloat16* BufL[2] = { (__nv_bfloat16*)(smem + OFF_B0L), (__nv_bfloat16*)(smem + OFF_B1L) };
    float* gbuf = (float*)(smem + OFF_B0H);   // 256 x GBS, overlays both B buffers (dead at scatter)

    const int t = threadIdx.x;
    const int w = t >> 5, l = t & 31;
    const int h0 = blockIdx.x * 8;

    // resident Wh slice: 32 rows (gate*8 + hh) x 1024, hi+lo
    for (int i = t; i < 4096; i += 256) {
        int r = i >> 7;
        int c = (i & 127) * 8;
        int grow = ((r >> 3) << 10) + h0 + (r & 7);
        size_t g = (size_t)grow * HID + c;
        *(uint4*)&Ah[r * A_ST + c] = *(const uint4*)&g_wh_hi[g];
        *(uint4*)&Al[r * A_ST + c] = *(const uint4*)&g_wh_lo[g];
    }

    const int hh = t & 7, bb = t >> 3;
    const float bi  = bias[0 * HID + h0 + hh];
    const float bf_ = bias[1 * HID + h0 + hh];
    const float bo  = bias[2 * HID + h0 + hh];
    const float bc  = bias[3 * HID + h0 + hh];
    float c1 = 0.f, c2 = 0.f;

    const int q  = w;              // K-slice of 16 within each 128-chunk
    const int kq = q * 16;
    const int qr = l >> 2, tg = l & 3;
    const int a_rl  = l & 15;
    const int a_cs  = (l >> 4) * 8;
    const int b_rl  = (l & 7) + ((l >> 4) << 3);
    const int b_cs  = ((l >> 3) & 1) * 8;

    const int sr = t >> 4, scq = (t & 15) * 8;      // staging map

    __syncthreads();

    for (int s = 0; s < S_LEN; s++) {
        const int p = s & 1;
        const __nv_bfloat16* hsrc_hi = g_h_hi[p];
        const __nv_bfloat16* hsrc_lo = g_h_lo[p];

        // prefetch this step's x-projection values
        float xpv[4][2];
        {
            const size_t xpb = (size_t)s * ((size_t)NG * BATCH);
            const int h = h0 + hh;
#pragma unroll
            for (int g = 0; g < 4; g++) {
                size_t idx = xpb + (size_t)(g * HID + h) * BATCH + bb;
                xpv[g][0] = __ldg(&g_xp[idx]);
                xpv[g][1] = __ldg(&g_xp[idx + 32]);
            }
        }

        float acc[2][8][4];
#pragma unroll
        for (int i = 0; i < 2; i++)
#pragma unroll
            for (int j = 0; j < 8; j++)
#pragma unroll
                for (int k = 0; k < 4; k++) acc[i][j][k] = 0.f;

        auto stage = [&](int k0, int bs) {
#pragma unroll
            for (int j = 0; j < 4; j++) {
                int r = sr + j * 16;
                size_t g = (size_t)r * HID + k0 + scq;
                CPA(smem_u32(BufH[bs] + r * B_ST + scq), hsrc_hi + g);
                CPA(smem_u32(BufL[bs] + r * B_ST + scq), hsrc_lo + g);
            }
        };

        stage(0, 0);
        CP_COMMIT();

        for (int c = 0; c < 8; c++) {
            if (c < 7) {
                stage((c + 1) * 128, (c + 1) & 1);
                CP_COMMIT();
                CP_WAIT(1);
            } else {
                CP_WAIT(0);
            }
            __syncthreads();

            const __nv_bfloat16* Bh = BufH[c & 1];
            const __nv_bfloat16* Bl = BufL[c & 1];
            const int kg = c * 128 + kq;   // A col (global K)
            // loads: A 32 rows x K16 hi+lo, B 64 rows x K16 hi+lo
            uint32_t ah[2][4], al[2][4], bh[4][4], bl[4][4];
#pragma unroll
            for (int mt = 0; mt < 2; mt++) {
                ldsm4(ah[mt], &Ah[(mt * 16 + a_rl) * A_ST + kg + a_cs]);
                ldsm4(al[mt], &Al[(mt * 16 + a_rl) * A_ST + kg + a_cs]);
            }
#pragma unroll
            for (int bf = 0; bf < 4; bf++) {
                int n = bf * 16 + b_rl;
                ldsm4(bh[bf], &Bh[n * B_ST + kq + b_cs]);
                ldsm4(bl[bf], &Bl[n * B_ST + kq + b_cs]);
            }
            // term-major: 16 independent acc chains
#pragma unroll
            for (int no = 0; no < 8; no++) {
                const uint32_t* bf = &bh[no >> 1][(no & 1) * 2];
                mma16816(acc[0][no], ah[0], bf);
                mma16816(acc[1][no], ah[1], bf);
            }
#pragma unroll
            for (int no = 0; no < 8; no++) {
                const uint32_t* bf = &bl[no >> 1][(no & 1) * 2];
                mma16816(acc[0][no], ah[0], bf);
                mma16816(acc[1][no], ah[1], bf);
            }
#pragma unroll
            for (int no = 0; no < 8; no++) {
                const uint32_t* bf = &bh[no >> 1][(no & 1) * 2];
                mma16816(acc[0][no], al[0], bf);
                mma16816(acc[1][no], al[1], bf);
            }
            __syncthreads();
        }

        // scatter K-partials: gbuf[(q*32 + row)*GBS + col]
#pragma unroll
        for (int mt = 0; mt < 2; mt++) {
#pragma unroll
            for (int no = 0; no < 8; no++) {
                int row = q * 32 + mt * 16 + qr;
                int col = no * 8 + tg * 2;
                float* g0 = &gbuf[row * GBS + col];
                g0[0] = acc[mt][no][0];
                g0[1] = acc[mt][no][1];
                g0[GBS * 8]     = acc[mt][no][2];
                g0[GBS * 8 + 1] = acc[mt][no][3];
            }
        }
        __syncthreads();

        // pointwise: 2 cells per thread; sum 8 K-slices per gate
        {
            const int h = h0 + hh;
#pragma unroll
            for (int cc = 0; cc < 2; cc++) {
                int b = bb + cc * 32;
                float gi = xpv[0][cc] + bi;
                float gf = xpv[1][cc] + bf_;
                float go = xpv[2][cc] + bo;
                float gc = xpv[3][cc] + bc;
#pragma unroll
                for (int qq = 0; qq < 8; qq++) {
                    gi += gbuf[(qq * 32 + 0 * 8 + hh) * GBS + b];
                    gf += gbuf[(qq * 32 + 1 * 8 + hh) * GBS + b];
                    go += gbuf[(qq * 32 + 2 * 8 + hh) * GBS + b];
                    gc += gbuf[(qq * 32 + 3 * 8 + hh) * GBS + b];
                }

                float it = 1.f / (1.f + expf(-gi));
                float ft = 1.f / (1.f + expf(-gf));
                float ot = 1.f / (1.f + expf(-go));
                float ch = tanhf(gc);

                float cprev = cc ? c2 : c1;
                float cn = ft * cprev + it * ch;
                float hn = ot * tanhf(cn);
                if (cc) c2 = cn; else c1 = cn;

                int ci = b * HID + h;
                __nv_bfloat16 hhi = __float2bfloat16_rn(hn);
                g_h_hi[p ^ 1][ci] = hhi;
                g_h_lo[p ^ 1][ci] = __float2bfloat16_rn(hn - __bfloat162float(hhi));
                out[((size_t)b * S_LEN + s) * HID + h] = hn;
                if (s == S_LEN - 1) g_c[ci] = cn;
            }
        }

        // flag-array grid barrier (no atomic serialization)
        if (s < S_LEN - 1) {
            __syncthreads();
            if (t == 0) {
                __threadfence();
                asm volatile("st.release.gpu.u32 [%0], %1;"
                             :: "l"(&g_flags[blockIdx.x]), "r"((unsigned)(s + 1)) : "memory");
            }
            if (t < NBLK) {
                unsigned v;
                do {
                    asm volatile("ld.acquire.gpu.u32 %0, [%1];" : "=r"(v) : "l"(&g_flags[t]));
                } while (v < (unsigned)(s + 1));
            }
            __syncthreads();
        }
    }
}

// ---------------- finalize ----------------
__global__ void finalize_kernel(float* __restrict__ out) {
    int i = blockIdx.x * blockDim.x + threadIdx.x;
    if (i < BATCH * HID) {
        int b = i / HID, h = i % HID;
        const size_t OUT0 = (size_t)BATCH * S_LEN * HID;
        out[OUT0 + i]               = out[((size_t)b * S_LEN + (S_LEN - 1)) * HID + h];
        out[OUT0 + BATCH * HID + i] = g_c[i];
    }
}

// ---------------- launch ----------------
extern "C" void kernel_launch(void* const* d_in, const int* in_sizes, int n_in,
                              void* d_out, int out_size) {
    const float* inp  = (const float*)d_in[0];
    const float* Wx   = (const float*)d_in[1];
    const float* Wh   = (const float*)d_in[2];
    const float* bias = (const float*)d_in[3];
    float* out = (float*)d_out;

    void *p_in_hi, *p_in_lo, *p_wx_hi, *p_wx_lo, *p_wh_hi, *p_wh_lo;
    cudaGetSymbolAddress(&p_in_hi, g_in_hi);
    cudaGetSymbolAddress(&p_in_lo, g_in_lo);
    cudaGetSymbolAddress(&p_wx_hi, g_wx_hi);
    cudaGetSymbolAddress(&p_wx_lo, g_wx_lo);
    cudaGetSymbolAddress(&p_wh_hi, g_wh_hi);
    cudaGetSymbolAddress(&p_wh_lo, g_wh_lo);

    static int configured = 0;
    if (!configured) {
        cudaFuncSetAttribute(lstm_rec_kernel,
                             cudaFuncAttributeMaxDynamicSharedMemorySize, SMEM_REC);
        cudaFuncSetAttribute(xproj_kernel,
                             cudaFuncAttributeMaxDynamicSharedMemorySize, SMEM_XP);
        configured = 1;
    }

    const size_t n_inp = (size_t)BATCH * S_LEN * DIM;
    const size_t n_w   = (size_t)NG * DIM;

    split_kernel<<<(unsigned)((n_inp + 255) / 256), 256>>>(
        inp, (__nv_bfloat16*)p_in_hi, (__nv_bfloat16*)p_in_lo, n_inp);
    split_kernel<<<(unsigned)((n_w + 255) / 256), 256>>>(
        Wx, (__nv_bfloat16*)p_wx_hi, (__nv_bfloat16*)p_wx_lo, n_w);
    split_kernel<<<(unsigned)((n_w + 255) / 256), 256>>>(
        Wh, (__nv_bfloat16*)p_wh_hi, (__nv_bfloat16*)p_wh_lo, n_w);
    init_kernel<<<(BATCH * HID + 255) / 256, 256>>>();

    dim3 xg(NG / 128, S_LEN / 2);
    xproj_kernel<<<xg, 256, SMEM_XP>>>();

    lstm_rec_kernel<<<NBLK, 256, SMEM_REC>>>(bias, out);

    if ((size_t)out_size >= (size_t)BATCH * S_LEN * HID + 2 * BATCH * HID)
        finalize_kernel<<<(BATCH * HID + 255) / 256, 256>>>(out);
}

// round 9
// speedup vs baseline: 1.1074x; 1.1074x over previous
#include <cuda_runtime.h>
#include <cuda_bf16.h>
#include <stdint.h>

// Problem dims
#define S_LEN 512
#define BATCH 64
#define DIM   1024
#define HID   1024
#define NG    4096
#define NBLK  128    // persistent recurrence blocks

#define A_ST  1032   // Wh smem row stride (bf16)
#define B_ST  136    // h-chunk smem row stride (bf16)

// recurrence smem layout (bytes)
#define OFF_AL  66048           // 32*A_ST*2
#define OFF_B0H 132096
#define OFF_B0L 149504
#define OFF_B1H 166912
#define OFF_B1L 184320
#define SMEM_REC 201728
#define GBS 68                  // gbuf row stride (floats)

// xproj smem: 2 buffers x 20480 bf16 (Ah 0 / Al 5120 / Bh 10240 / Bl 15360), stride 40
#define XA_ST 40
#define XBUF_ELEMS 20480
#define SMEM_XP (2 * XBUF_ELEMS * 2)

// ---------------- device global scratch ----------------
__device__ __nv_bfloat16 g_in_hi[(size_t)BATCH * S_LEN * DIM];
__device__ __nv_bfloat16 g_in_lo[(size_t)BATCH * S_LEN * DIM];
__device__ __nv_bfloat16 g_wx_hi[(size_t)NG * DIM];
__device__ __nv_bfloat16 g_wx_lo[(size_t)NG * DIM];
__device__ __nv_bfloat16 g_wh_hi[(size_t)NG * HID];
__device__ __nv_bfloat16 g_wh_lo[(size_t)NG * HID];
__device__ float         g_xp[(size_t)S_LEN * NG * BATCH];   // [s][n][b]
__device__ float         g_c[BATCH * HID];
__device__ __nv_bfloat16 g_h_hi[2][BATCH * HID];
__device__ __nv_bfloat16 g_h_lo[2][BATCH * HID];
__device__ unsigned      g_flags[NBLK];                      // flag-array grid barrier

// ---------------- helpers ----------------
__device__ __forceinline__ void mma16816(float* c, const uint32_t* a, const uint32_t* b) {
    asm volatile(
        "mma.sync.aligned.m16n8k16.row.col.f32.bf16.bf16.f32 "
        "{%0,%1,%2,%3}, {%4,%5,%6,%7}, {%8,%9}, {%0,%1,%2,%3};\n"
        : "+f"(c[0]), "+f"(c[1]), "+f"(c[2]), "+f"(c[3])
        : "r"(a[0]), "r"(a[1]), "r"(a[2]), "r"(a[3]), "r"(b[0]), "r"(b[1]));
}
__device__ __forceinline__ void ldsm4(uint32_t* r, const void* p) {
    uint32_t addr = (uint32_t)__cvta_generic_to_shared(p);
    asm volatile("ldmatrix.sync.aligned.m8n8.x4.shared.b16 {%0,%1,%2,%3}, [%4];"
                 : "=r"(r[0]), "=r"(r[1]), "=r"(r[2]), "=r"(r[3]) : "r"(addr));
}
__device__ __forceinline__ uint32_t smem_u32(const void* p) {
    return (uint32_t)__cvta_generic_to_shared(p);
}
#define CPA(dst, src) asm volatile("cp.async.cg.shared.global [%0], [%1], 16;\n" :: "r"(dst), "l"(src))
#define CP_COMMIT()   asm volatile("cp.async.commit_group;\n")
#define CP_WAIT(n)    asm volatile("cp.async.wait_group %0;\n" :: "n"(n))

__global__ void split_kernel(const float* __restrict__ src,
                             __nv_bfloat16* __restrict__ hi,
                             __nv_bfloat16* __restrict__ lo, size_t n) {
    size_t i = (size_t)blockIdx.x * blockDim.x + threadIdx.x;
    if (i < n) {
        float v = src[i];
        __nv_bfloat16 h = __float2bfloat16_rn(v);
        hi[i] = h;
        lo[i] = __float2bfloat16_rn(v - __bfloat162float(h));
    }
}

__global__ void init_kernel() {
    int i = blockIdx.x * blockDim.x + threadIdx.x;
    if (i < NBLK) g_flags[i] = 0u;
    if (i < BATCH * HID) {
        __nv_bfloat16 z = __float2bfloat16_rn(0.f);
        g_h_hi[0][i] = z; g_h_lo[0][i] = z;
        g_h_hi[1][i] = z; g_h_lo[1][i] = z;
    }
}

// ---------------- x-projection GEMM (validated R3) ----------------
__global__ void __launch_bounds__(256, 2) xproj_kernel() {
    extern __shared__ __align__(16) __nv_bfloat16 xs[];
    const int s0 = blockIdx.y * 2;
    const int n0 = blockIdx.x * 128;
    const int t  = threadIdx.x;
    const int w  = t >> 5, l = t & 31;
    const int wm = (w & 3) * 32;
    const int wc = (w >> 2) * 64;

    float acc[2][8][4];
#pragma unroll
    for (int i = 0; i < 2; i++)
#pragma unroll
        for (int j = 0; j < 8; j++)
#pragma unroll
            for (int k = 0; k < 4; k++) acc[i][j][k] = 0.f;

    const int lr  = t >> 2;
    const int lcq = (t & 3) * 8;
    const int qr = l >> 2, tg = l & 3;
    const int a_col = (l >> 4) * 8;
    const int b_col = ((l >> 3) & 1) * 8;

    auto stage = [&](int k0, int bs) {
        __nv_bfloat16* base = xs + bs * XBUF_ELEMS;
#pragma unroll
        for (int j = 0; j < 2; j++) {
            int r = lr + j * 64;
            size_t ga = (size_t)(n0 + r) * DIM + k0 + lcq;
            CPA(smem_u32(base + r * XA_ST + lcq),        g_wx_hi + ga);
            CPA(smem_u32(base + 5120 + r * XA_ST + lcq), g_wx_lo + ga);
            int b = r & 63, sl = r >> 6;
            size_t gb = ((size_t)b * S_LEN + s0 + sl) * DIM + k0 + lcq;
            CPA(smem_u32(base + 10240 + r * XA_ST + lcq), g_in_hi + gb);
            CPA(smem_u32(base + 15360 + r * XA_ST + lcq), g_in_lo + gb);
        }
    };

    stage(0, 0);
    CP_COMMIT();

    const int NCH = DIM / 32;
    for (int c = 0; c < NCH; c++) {
        if (c + 1 < NCH) {
            stage((c + 1) * 32, (c + 1) & 1);
            CP_COMMIT();
            CP_WAIT(1);
        } else {
            CP_WAIT(0);
        }
        __syncthreads();
        const __nv_bfloat16* base = xs + (c & 1) * XBUF_ELEMS;
#pragma unroll
        for (int kk = 0; kk < 32; kk += 16) {
            uint32_t ah[2][4], al[2][4];
#pragma unroll
            for (int mt = 0; mt < 2; mt++) {
                int a_row = wm + mt * 16 + (l & 15);
                ldsm4(ah[mt], base + a_row * XA_ST + kk + a_col);
                ldsm4(al[mt], base + 5120 + a_row * XA_ST + kk + a_col);
            }
#pragma unroll
            for (int bg = 0; bg < 4; bg++) {
                int b_row = wc + bg * 16 + (l & 7) + ((l >> 4) << 3);
                uint32_t bh[4], bl[4];
                ldsm4(bh, base + 10240 + b_row * XA_ST + kk + b_col);
                ldsm4(bl, base + 15360 + b_row * XA_ST + kk + b_col);
                float* a00 = acc[0][2 * bg];
                float* a01 = acc[0][2 * bg + 1];
                float* a10 = acc[1][2 * bg];
                float* a11 = acc[1][2 * bg + 1];
                mma16816(a00, ah[0], &bh[0]); mma16816(a10, ah[1], &bh[0]);
                mma16816(a01, ah[0], &bh[2]); mma16816(a11, ah[1], &bh[2]);
                mma16816(a00, ah[0], &bl[0]); mma16816(a10, ah[1], &bl[0]);
                mma16816(a01, ah[0], &bl[2]); mma16816(a11, ah[1], &bl[2]);
                mma16816(a00, al[0], &bh[0]); mma16816(a10, al[1], &bh[0]);
                mma16816(a01, al[0], &bh[2]); mma16816(a11, al[1], &bh[2]);
            }
        }
        __syncthreads();
    }

#pragma unroll
    for (int mt = 0; mt < 2; mt++) {
#pragma unroll
        for (int bg = 0; bg < 4; bg++) {
#pragma unroll
            for (int half = 0; half < 2; half++) {
                const float* a = acc[mt][2 * bg + half];
                int n = n0 + wm + mt * 16 + qr;
                int cc = wc + bg * 16 + half * 8 + tg * 2;
                int s = s0 + (cc >> 6);
                int b = cc & 63;
                size_t base = ((size_t)s * NG + n) * BATCH + b;
                *(float2*)&g_xp[base]             = make_float2(a[0], a[1]);
                *(float2*)&g_xp[base + 8 * BATCH] = make_float2(a[2], a[3]);
            }
        }
    }
}

// ---------------- persistent recurrence kernel (32x32 warp tiles, K-split 4) ----------------
// 128 blocks x 256 threads. Block: 32 gate rows (4 gates x 8 h, h0=blk*8) x 64 batch.
// Warp w: n-half = w&1 (32 cols), K-quarter q = w>>1 (K = [32q,32q+32) of each chunk).
__global__ void __launch_bounds__(256) lstm_rec_kernel(const float* __restrict__ bias,
                                                       float* __restrict__ out) {
    extern __shared__ __align__(16) char smem[];
    __nv_bfloat16* Ah = (__nv_bfloat16*)(smem);
    __nv_bfloat16* Al = (__nv_bfloat16*)(smem + OFF_AL);
    __nv_bfloat16* BufH[2] = { (__nv_bfloat16*)(smem + OFF_B0H), (__nv_bfloat16*)(smem + OFF_B1H) };
    __nv_bfloat16* BufL[2] = { (__nv_bfloat16*)(smem + OFF_B0L), (__nv_bfloat16*)(smem + OFF_B1L) };
    float* gbuf = (float*)(smem + OFF_B0H);   // overlays buffer 0 during epilogue (safe)

    const int t = threadIdx.x;
    const int w = t >> 5, l = t & 31;
    const int h0 = blockIdx.x * 8;

    // resident Wh slice: 32 rows (gate*8 + hh) x 1024, hi+lo
    for (int i = t; i < 4096; i += 256) {
        int r = i >> 7;
        int c = (i & 127) * 8;
        int grow = ((r >> 3) << 10) + h0 + (r & 7);
        size_t g = (size_t)grow * HID + c;
        *(uint4*)&Ah[r * A_ST + c] = *(const uint4*)&g_wh_hi[g];
        *(uint4*)&Al[r * A_ST + c] = *(const uint4*)&g_wh_lo[g];
    }

    const int hh = t & 7, bb = t >> 3;
    const float bi  = bias[0 * HID + h0 + hh];
    const float bf_ = bias[1 * HID + h0 + hh];
    const float bo  = bias[2 * HID + h0 + hh];
    const float bc  = bias[3 * HID + h0 + hh];
    float c1 = 0.f, c2 = 0.f;

    const int nh = w & 1;          // n-half (32 cols)
    const int q  = w >> 1;         // K-quarter
    const int qr = l >> 2, tg = l & 3;
    const int a_rl  = l & 15;
    const int a_cs  = (l >> 4) * 8;
    const int b_rl  = (l & 7) + ((l >> 4) << 3);
    const int b_cs  = ((l >> 3) & 1) * 8;
    const int kkb   = q * 32;

    const int sr = t >> 4, scq = (t & 15) * 8;      // staging map

    __syncthreads();

    for (int s = 0; s < S_LEN; s++) {
        const int p = s & 1;
        const __nv_bfloat16* hsrc_hi = g_h_hi[p];
        const __nv_bfloat16* hsrc_lo = g_h_lo[p];

        // prefetch this step's x-projection values
        float xpv[4][2];
        {
            const size_t xpb = (size_t)s * ((size_t)NG * BATCH);
            const int h = h0 + hh;
#pragma unroll
            for (int g = 0; g < 4; g++) {
                size_t idx = xpb + (size_t)(g * HID + h) * BATCH + bb;
                xpv[g][0] = __ldg(&g_xp[idx]);
                xpv[g][1] = __ldg(&g_xp[idx + 32]);
            }
        }

        float acc[2][4][4];
#pragma unroll
        for (int i = 0; i < 2; i++)
#pragma unroll
            for (int j = 0; j < 4; j++)
#pragma unroll
                for (int k = 0; k < 4; k++) acc[i][j][k] = 0.f;

        auto stage = [&](int k0, int bs) {
#pragma unroll
            for (int j = 0; j < 4; j++) {
                int r = sr + j * 16;
                size_t g = (size_t)r * HID + k0 + scq;
                CPA(smem_u32(BufH[bs] + r * B_ST + scq), hsrc_hi + g);
                CPA(smem_u32(BufL[bs] + r * B_ST + scq), hsrc_lo + g);
            }
        };

        stage(0, 0);
        CP_COMMIT();

        for (int c = 0; c < 8; c++) {
            if (c < 7) {
                stage((c + 1) * 128, (c + 1) & 1);
                CP_COMMIT();
                CP_WAIT(1);
            } else {
                CP_WAIT(0);
            }
            __syncthreads();

            const __nv_bfloat16* Bh = BufH[c & 1];
            const __nv_bfloat16* Bl = BufL[c & 1];
            const int k0 = c * 128;
#pragma unroll
            for (int j = 0; j < 2; j++) {
                const int kg = k0 + kkb + j * 16;   // A col (global K)
                const int kl = kkb + j * 16;        // B col (chunk-local)
                uint32_t ah[2][4], al[2][4], bh[2][4], bl[2][4];
#pragma unroll
                for (int mt = 0; mt < 2; mt++) {
                    ldsm4(ah[mt], &Ah[(mt * 16 + a_rl) * A_ST + kg + a_cs]);
                    ldsm4(al[mt], &Al[(mt * 16 + a_rl) * A_ST + kg + a_cs]);
                }
#pragma unroll
                for (int bf = 0; bf < 2; bf++) {
                    int n = nh * 32 + bf * 16 + b_rl;
                    ldsm4(bh[bf], &Bh[n * B_ST + kl + b_cs]);
                    ldsm4(bl[bf], &Bl[n * B_ST + kl + b_cs]);
                }
                // term-major: 8 independent acc chains
#pragma unroll
                for (int no = 0; no < 4; no++) {
                    const uint32_t* bf = &bh[no >> 1][(no & 1) * 2];
                    mma16816(acc[0][no], ah[0], bf);
                    mma16816(acc[1][no], ah[1], bf);
                }
#pragma unroll
                for (int no = 0; no < 4; no++) {
                    const uint32_t* bf = &bl[no >> 1][(no & 1) * 2];
                    mma16816(acc[0][no], ah[0], bf);
                    mma16816(acc[1][no], ah[1], bf);
                }
#pragma unroll
                for (int no = 0; no < 4; no++) {
                    const uint32_t* bf = &bh[no >> 1][(no & 1) * 2];
                    mma16816(acc[0][no], al[0], bf);
                    mma16816(acc[1][no], al[1], bf);
                }
            }
            __syncthreads();
        }

        // scatter K-partials: gbuf[(q*32 + row)*GBS + col]
#pragma unroll
        for (int mt = 0; mt < 2; mt++) {
#pragma unroll
            for (int no = 0; no < 4; no++) {
                int row = mt * 16 + qr;
                int col = nh * 32 + no * 8 + tg * 2;
                float* g0 = &gbuf[(q * 32 + row) * GBS + col];
                g0[0] = acc[mt][no][0];
                g0[1] = acc[mt][no][1];
                g0[GBS * 8]     = acc[mt][no][2];
                g0[GBS * 8 + 1] = acc[mt][no][3];
            }
        }
        __syncthreads();

        // pointwise: 2 cells per thread; sum 4 K-quarters per gate
        {
            const int h = h0 + hh;
#pragma unroll
            for (int cc = 0; cc < 2; cc++) {
                int b = bb + cc * 32;
                float gi = xpv[0][cc] + bi;
                float gf = xpv[1][cc] + bf_;
                float go = xpv[2][cc] + bo;
                float gc = xpv[3][cc] + bc;
#pragma unroll
                for (int qq = 0; qq < 4; qq++) {
                    gi += gbuf[(qq * 32 + 0 * 8 + hh) * GBS + b];
                    gf += gbuf[(qq * 32 + 1 * 8 + hh) * GBS + b];
                    go += gbuf[(qq * 32 + 2 * 8 + hh) * GBS + b];
                    gc += gbuf[(qq * 32 + 3 * 8 + hh) * GBS + b];
                }

                float it = 1.f / (1.f + expf(-gi));
                float ft = 1.f / (1.f + expf(-gf));
                float ot = 1.f / (1.f + expf(-go));
                float ch = tanhf(gc);

                float cprev = cc ? c2 : c1;
                float cn = ft * cprev + it * ch;
                float hn = ot * tanhf(cn);
                if (cc) c2 = cn; else c1 = cn;

                int ci = b * HID + h;
                __nv_bfloat16 hhi = __float2bfloat16_rn(hn);
                g_h_hi[p ^ 1][ci] = hhi;
                g_h_lo[p ^ 1][ci] = __float2bfloat16_rn(hn - __bfloat162float(hhi));
                out[((size_t)b * S_LEN + s) * HID + h] = hn;
                if (s == S_LEN - 1) g_c[ci] = cn;
            }
        }

        // flag-array grid barrier (distinct addresses -> no atomic serialization)
        if (s < S_LEN - 1) {
            __syncthreads();
            if (t == 0) {
                __threadfence();
                asm volatile("st.release.gpu.u32 [%0], %1;"
                             :: "l"(&g_flags[blockIdx.x]), "r"((unsigned)(s + 1)) : "memory");
            }
            if (t < NBLK) {
                unsigned v;
                do {
                    asm volatile("ld.acquire.gpu.u32 %0, [%1];" : "=r"(v) : "l"(&g_flags[t]));
                } while (v < (unsigned)(s + 1));
            }
            __syncthreads();
        }
    }
}

// ---------------- finalize ----------------
__global__ void finalize_kernel(float* __restrict__ out) {
    int i = blockIdx.x * blockDim.x + threadIdx.x;
    if (i < BATCH * HID) {
        int b = i / HID, h = i % HID;
        const size_t OUT0 = (size_t)BATCH * S_LEN * HID;
        out[OUT0 + i]               = out[((size_t)b * S_LEN + (S_LEN - 1)) * HID + h];
        out[OUT0 + BATCH * HID + i] = g_c[i];
    }
}

// ---------------- launch ----------------
extern "C" void kernel_launch(void* const* d_in, const int* in_sizes, int n_in,
                              void* d_out, int out_size) {
    const float* inp  = (const float*)d_in[0];
    const float* Wx   = (const float*)d_in[1];
    const float* Wh   = (const float*)d_in[2];
    const float* bias = (const float*)d_in[3];
    float* out = (float*)d_out;

    void *p_in_hi, *p_in_lo, *p_wx_hi, *p_wx_lo, *p_wh_hi, *p_wh_lo;
    cudaGetSymbolAddress(&p_in_hi, g_in_hi);
    cudaGetSymbolAddress(&p_in_lo, g_in_lo);
    cudaGetSymbolAddress(&p_wx_hi, g_wx_hi);
    cudaGetSymbolAddress(&p_wx_lo, g_wx_lo);
    cudaGetSymbolAddress(&p_wh_hi, g_wh_hi);
    cudaGetSymbolAddress(&p_wh_lo, g_wh_lo);

    static int configured = 0;
    if (!configured) {
        cudaFuncSetAttribute(lstm_rec_kernel,
                             cudaFuncAttributeMaxDynamicSharedMemorySize, SMEM_REC);
        cudaFuncSetAttribute(xproj_kernel,
                             cudaFuncAttributeMaxDynamicSharedMemorySize, SMEM_XP);
        configured = 1;
    }

    const size_t n_inp = (size_t)BATCH * S_LEN * DIM;
    const size_t n_w   = (size_t)NG * DIM;

    split_kernel<<<(unsigned)((n_inp + 255) / 256), 256>>>(
        inp, (__nv_bfloat16*)p_in_hi, (__nv_bfloat16*)p_in_lo, n_inp);
    split_kernel<<<(unsigned)((n_w + 255) / 256), 256>>>(
        Wx, (__nv_bfloat16*)p_wx_hi, (__nv_bfloat16*)p_wx_lo, n_w);
    split_kernel<<<(unsigned)((n_w + 255) / 256), 256>>>(
        Wh, (__nv_bfloat16*)p_wh_hi, (__nv_bfloat16*)p_wh_lo, n_w);
    init_kernel<<<(BATCH * HID + 255) / 256, 256>>>();

    dim3 xg(NG / 128, S_LEN / 2);
    xproj_kernel<<<xg, 256, SMEM_XP>>>();

    lstm_rec_kernel<<<NBLK, 256, SMEM_REC>>>(bias, out);

    if ((size_t)out_size >= (size_t)BATCH * S_LEN * HID + 2 * BATCH * HID)
        finalize_kernel<<<(BATCH * HID + 255) / 256, 256>>>(out);
}

// round 10
// speedup vs baseline: 1.4776x; 1.3343x over previous
#include <cuda_runtime.h>
#include <cuda_bf16.h>
#include <stdint.h>

// Problem dims
#define S_LEN 512
#define BATCH 64
#define DIM   1024
#define HID   1024
#define NG    4096
#define NBLK  128    // persistent recurrence blocks

#define A_ST  1032   // Wh smem row stride (bf16)
#define B_ST  136    // h-chunk smem row stride (bf16)

// recurrence smem layout (bytes)
#define OFF_AL  66048           // 32*A_ST*2
#define OFF_B0H 132096
#define OFF_B0L 149504
#define OFF_B1H 166912
#define OFF_B1L 184320
#define SMEM_REC 201728
#define GBS 68                  // gbuf row stride (floats); 256 rows overlay both B buffers

// xproj smem: 2 buffers x 20480 bf16 (Ah 0 / Al 5120 / Bh 10240 / Bl 15360), stride 40
#define XA_ST 40
#define XBUF_ELEMS 20480
#define SMEM_XP (2 * XBUF_ELEMS * 2)

// ---------------- device global scratch ----------------
__device__ __nv_bfloat16 g_in_hi[(size_t)BATCH * S_LEN * DIM];
__device__ __nv_bfloat16 g_in_lo[(size_t)BATCH * S_LEN * DIM];
__device__ __nv_bfloat16 g_wx_hi[(size_t)NG * DIM];
__device__ __nv_bfloat16 g_wx_lo[(size_t)NG * DIM];
__device__ __nv_bfloat16 g_wh_hi[(size_t)NG * HID];
__device__ __nv_bfloat16 g_wh_lo[(size_t)NG * HID];
__device__ float         g_xp[(size_t)S_LEN * NG * BATCH];   // [s][n][b]
__device__ float         g_c[BATCH * HID];
__device__ __nv_bfloat16 g_h_hi[2][BATCH * HID];
__device__ __nv_bfloat16 g_h_lo[2][BATCH * HID];
__device__ unsigned      g_bar_cnt;                          // monotonic grid-barrier counter

// ---------------- helpers ----------------
__device__ __forceinline__ void mma16816(float* c, const uint32_t* a, const uint32_t* b) {
    asm volatile(
        "mma.sync.aligned.m16n8k16.row.col.f32.bf16.bf16.f32 "
        "{%0,%1,%2,%3}, {%4,%5,%6,%7}, {%8,%9}, {%0,%1,%2,%3};\n"
        : "+f"(c[0]), "+f"(c[1]), "+f"(c[2]), "+f"(c[3])
        : "r"(a[0]), "r"(a[1]), "r"(a[2]), "r"(a[3]), "r"(b[0]), "r"(b[1]));
}
__device__ __forceinline__ void ldsm4(uint32_t* r, const void* p) {
    uint32_t addr = (uint32_t)__cvta_generic_to_shared(p);
    asm volatile("ldmatrix.sync.aligned.m8n8.x4.shared.b16 {%0,%1,%2,%3}, [%4];"
                 : "=r"(r[0]), "=r"(r[1]), "=r"(r[2]), "=r"(r[3]) : "r"(addr));
}
__device__ __forceinline__ uint32_t smem_u32(const void* p) {
    return (uint32_t)__cvta_generic_to_shared(p);
}
#define CPA(dst, src) asm volatile("cp.async.cg.shared.global [%0], [%1], 16;\n" :: "r"(dst), "l"(src))
#define CP_COMMIT()   asm volatile("cp.async.commit_group;\n")
#define CP_WAIT(n)    asm volatile("cp.async.wait_group %0;\n" :: "n"(n))

__global__ void split_kernel(const float* __restrict__ src,
                             __nv_bfloat16* __restrict__ hi,
                             __nv_bfloat16* __restrict__ lo, size_t n) {
    size_t i = (size_t)blockIdx.x * blockDim.x + threadIdx.x;
    if (i < n) {
        float v = src[i];
        __nv_bfloat16 h = __float2bfloat16_rn(v);
        hi[i] = h;
        lo[i] = __float2bfloat16_rn(v - __bfloat162float(h));
    }
}

__global__ void init_kernel() {
    int i = blockIdx.x * blockDim.x + threadIdx.x;
    if (i == 0) g_bar_cnt = 0;
    if (i < BATCH * HID) {
        __nv_bfloat16 z = __float2bfloat16_rn(0.f);
        g_h_hi[0][i] = z; g_h_lo[0][i] = z;
        g_h_hi[1][i] = z; g_h_lo[1][i] = z;
    }
}

// ---------------- x-projection GEMM (validated R3) ----------------
__global__ void __launch_bounds__(256, 2) xproj_kernel() {
    extern __shared__ __align__(16) __nv_bfloat16 xs[];
    const int s0 = blockIdx.y * 2;
    const int n0 = blockIdx.x * 128;
    const int t  = threadIdx.x;
    const int w  = t >> 5, l = t & 31;
    const int wm = (w & 3) * 32;
    const int wc = (w >> 2) * 64;

    float acc[2][8][4];
#pragma unroll
    for (int i = 0; i < 2; i++)
#pragma unroll
        for (int j = 0; j < 8; j++)
#pragma unroll
            for (int k = 0; k < 4; k++) acc[i][j][k] = 0.f;

    const int lr  = t >> 2;
    const int lcq = (t & 3) * 8;
    const int qr = l >> 2, tg = l & 3;
    const int a_col = (l >> 4) * 8;
    const int b_col = ((l >> 3) & 1) * 8;

    auto stage = [&](int k0, int bs) {
        __nv_bfloat16* base = xs + bs * XBUF_ELEMS;
#pragma unroll
        for (int j = 0; j < 2; j++) {
            int r = lr + j * 64;
            size_t ga = (size_t)(n0 + r) * DIM + k0 + lcq;
            CPA(smem_u32(base + r * XA_ST + lcq),        g_wx_hi + ga);
            CPA(smem_u32(base + 5120 + r * XA_ST + lcq), g_wx_lo + ga);
            int b = r & 63, sl = r >> 6;
            size_t gb = ((size_t)b * S_LEN + s0 + sl) * DIM + k0 + lcq;
            CPA(smem_u32(base + 10240 + r * XA_ST + lcq), g_in_hi + gb);
            CPA(smem_u32(base + 15360 + r * XA_ST + lcq), g_in_lo + gb);
        }
    };

    stage(0, 0);
    CP_COMMIT();

    const int NCH = DIM / 32;
    for (int c = 0; c < NCH; c++) {
        if (c + 1 < NCH) {
            stage((c + 1) * 32, (c + 1) & 1);
            CP_COMMIT();
            CP_WAIT(1);
        } else {
            CP_WAIT(0);
        }
        __syncthreads();
        const __nv_bfloat16* base = xs + (c & 1) * XBUF_ELEMS;
#pragma unroll
        for (int kk = 0; kk < 32; kk += 16) {
            uint32_t ah[2][4], al[2][4];
#pragma unroll
            for (int mt = 0; mt < 2; mt++) {
                int a_row = wm + mt * 16 + (l & 15);
                ldsm4(ah[mt], base + a_row * XA_ST + kk + a_col);
                ldsm4(al[mt], base + 5120 + a_row * XA_ST + kk + a_col);
            }
#pragma unroll
            for (int bg = 0; bg < 4; bg++) {
                int b_row = wc + bg * 16 + (l & 7) + ((l >> 4) << 3);
                uint32_t bh[4], bl[4];
                ldsm4(bh, base + 10240 + b_row * XA_ST + kk + b_col);
                ldsm4(bl, base + 15360 + b_row * XA_ST + kk + b_col);
                float* a00 = acc[0][2 * bg];
                float* a01 = acc[0][2 * bg + 1];
                float* a10 = acc[1][2 * bg];
                float* a11 = acc[1][2 * bg + 1];
                mma16816(a00, ah[0], &bh[0]); mma16816(a10, ah[1], &bh[0]);
                mma16816(a01, ah[0], &bh[2]); mma16816(a11, ah[1], &bh[2]);
                mma16816(a00, ah[0], &bl[0]); mma16816(a10, ah[1], &bl[0]);
                mma16816(a01, ah[0], &bl[2]); mma16816(a11, ah[1], &bl[2]);
                mma16816(a00, al[0], &bh[0]); mma16816(a10, al[1], &bh[0]);
                mma16816(a01, al[0], &bh[2]); mma16816(a11, al[1], &bh[2]);
            }
        }
        __syncthreads();
    }

#pragma unroll
    for (int mt = 0; mt < 2; mt++) {
#pragma unroll
        for (int bg = 0; bg < 4; bg++) {
#pragma unroll
            for (int half = 0; half < 2; half++) {
                const float* a = acc[mt][2 * bg + half];
                int n = n0 + wm + mt * 16 + qr;
                int cc = wc + bg * 16 + half * 8 + tg * 2;
                int s = s0 + (cc >> 6);
                int b = cc & 63;
                size_t base = ((size_t)s * NG + n) * BATCH + b;
                *(float2*)&g_xp[base]             = make_float2(a[0], a[1]);
                *(float2*)&g_xp[base + 8 * BATCH] = make_float2(a[2], a[3]);
            }
        }
    }
}

// ---------------- persistent recurrence kernel ----------------
// 128 blocks x 512 threads (16 warps, 4/SMSP). Block: 32 gate rows x 64 batch.
// Warp w: n-half nh = w&1 (32 cols), K-slice q = w>>1 (K16 of each 128-chunk).
// Per-warp state identical to the 6990us config (no spill risk).
__global__ void __launch_bounds__(512) lstm_rec_kernel(const float* __restrict__ bias,
                                                       float* __restrict__ out) {
    extern __shared__ __align__(16) char smem[];
    __nv_bfloat16* Ah = (__nv_bfloat16*)(smem);
    __nv_bfloat16* Al = (__nv_bfloat16*)(smem + OFF_AL);
    __nv_bfloat16* BufH[2] = { (__nv_bfloat16*)(smem + OFF_B0H), (__nv_bfloat16*)(smem + OFF_B1H) };
    __nv_bfloat16* BufL[2] = { (__nv_bfloat16*)(smem + OFF_B0L), (__nv_bfloat16*)(smem + OFF_B1L) };
    float* gbuf = (float*)(smem + OFF_B0H);   // 256 x GBS floats, overlays both B buffers (dead)

    const int t = threadIdx.x;
    const int w = t >> 5, l = t & 31;
    const int h0 = blockIdx.x * 8;

    // resident Wh slice: 32 rows (gate*8 + hh) x 1024, hi+lo
    for (int i = t; i < 4096; i += 512) {
        int r = i >> 7;
        int c = (i & 127) * 8;
        int grow = ((r >> 3) << 10) + h0 + (r & 7);
        size_t g = (size_t)grow * HID + c;
        *(uint4*)&Ah[r * A_ST + c] = *(const uint4*)&g_wh_hi[g];
        *(uint4*)&Al[r * A_ST + c] = *(const uint4*)&g_wh_lo[g];
    }

    // pointwise: 1 cell per thread
    const int hh = t & 7, bb = t >> 3;   // bb in 0..63
    const float bi  = bias[0 * HID + h0 + hh];
    const float bf_ = bias[1 * HID + h0 + hh];
    const float bo  = bias[2 * HID + h0 + hh];
    const float bc  = bias[3 * HID + h0 + hh];
    float cst = 0.f;

    const int nh = w & 1;          // n-half (32 cols)
    const int q  = w >> 1;         // K-slice (of 8)
    const int kq = q * 16;
    const int qr = l >> 2, tg = l & 3;
    const int a_rl  = l & 15;
    const int a_cs  = (l >> 4) * 8;
    const int b_rl  = (l & 7) + ((l >> 4) << 3);
    const int b_cs  = ((l >> 3) & 1) * 8;

    const int sr = t >> 4, scq = (t & 15) * 8;      // staging map (rows 0..31, +32)

    __syncthreads();

    for (int s = 0; s < S_LEN; s++) {
        const int p = s & 1;
        const __nv_bfloat16* hsrc_hi = g_h_hi[p];
        const __nv_bfloat16* hsrc_lo = g_h_lo[p];

        // prefetch this step's x-projection values
        float xpv[4];
        {
            const size_t xpb = (size_t)s * ((size_t)NG * BATCH);
            const int h = h0 + hh;
#pragma unroll
            for (int g = 0; g < 4; g++)
                xpv[g] = __ldg(&g_xp[xpb + (size_t)(g * HID + h) * BATCH + bb]);
        }

        float acc[2][4][4];
#pragma unroll
        for (int i = 0; i < 2; i++)
#pragma unroll
            for (int j = 0; j < 4; j++)
#pragma unroll
                for (int k = 0; k < 4; k++) acc[i][j][k] = 0.f;

        auto stage = [&](int k0, int bs) {
#pragma unroll
            for (int j = 0; j < 2; j++) {
                int r = sr + j * 32;
                size_t g = (size_t)r * HID + k0 + scq;
                CPA(smem_u32(BufH[bs] + r * B_ST + scq), hsrc_hi + g);
                CPA(smem_u32(BufL[bs] + r * B_ST + scq), hsrc_lo + g);
            }
        };

        stage(0, 0);
        CP_COMMIT();

        for (int c = 0; c < 8; c++) {
            if (c < 7) {
                stage((c + 1) * 128, (c + 1) & 1);
                CP_COMMIT();
                CP_WAIT(1);
            } else {
                CP_WAIT(0);
            }
            __syncthreads();

            const __nv_bfloat16* Bh = BufH[c & 1];
            const __nv_bfloat16* Bl = BufL[c & 1];
            const int kg = c * 128 + kq;   // A col (global K)
            uint32_t ah[2][4], al[2][4], bh[2][4], bl[2][4];
#pragma unroll
            for (int mt = 0; mt < 2; mt++) {
                ldsm4(ah[mt], &Ah[(mt * 16 + a_rl) * A_ST + kg + a_cs]);
                ldsm4(al[mt], &Al[(mt * 16 + a_rl) * A_ST + kg + a_cs]);
            }
#pragma unroll
            for (int bf = 0; bf < 2; bf++) {
                int n = nh * 32 + bf * 16 + b_rl;
                ldsm4(bh[bf], &Bh[n * B_ST + kq + b_cs]);
                ldsm4(bl[bf], &Bl[n * B_ST + kq + b_cs]);
            }
            // term-major: 8 independent acc chains
#pragma unroll
            for (int no = 0; no < 4; no++) {
                const uint32_t* bf = &bh[no >> 1][(no & 1) * 2];
                mma16816(acc[0][no], ah[0], bf);
                mma16816(acc[1][no], ah[1], bf);
            }
#pragma unroll
            for (int no = 0; no < 4; no++) {
                const uint32_t* bf = &bl[no >> 1][(no & 1) * 2];
                mma16816(acc[0][no], ah[0], bf);
                mma16816(acc[1][no], ah[1], bf);
            }
#pragma unroll
            for (int no = 0; no < 4; no++) {
                const uint32_t* bf = &bh[no >> 1][(no & 1) * 2];
                mma16816(acc[0][no], al[0], bf);
                mma16816(acc[1][no], al[1], bf);
            }
            __syncthreads();
        }

        // scatter K-partials: gbuf[(q*32 + row)*GBS + col], 256 rows total
#pragma unroll
        for (int mt = 0; mt < 2; mt++) {
#pragma unroll
            for (int no = 0; no < 4; no++) {
                int row = q * 32 + mt * 16 + qr;
                int col = nh * 32 + no * 8 + tg * 2;
                float* g0 = &gbuf[row * GBS + col];
                g0[0] = acc[mt][no][0];
                g0[1] = acc[mt][no][1];
                g0[GBS * 8]     = acc[mt][no][2];
                g0[GBS * 8 + 1] = acc[mt][no][3];
            }
        }
        __syncthreads();

        // pointwise: 1 cell per thread; sum 8 K-slices per gate
        {
            const int h = h0 + hh;
            float gi = xpv[0] + bi;
            float gf = xpv[1] + bf_;
            float go = xpv[2] + bo;
            float gc = xpv[3] + bc;
#pragma unroll
            for (int qq = 0; qq < 8; qq++) {
                gi += gbuf[(qq * 32 + 0 * 8 + hh) * GBS + bb];
                gf += gbuf[(qq * 32 + 1 * 8 + hh) * GBS + bb];
                go += gbuf[(qq * 32 + 2 * 8 + hh) * GBS + bb];
                gc += gbuf[(qq * 32 + 3 * 8 + hh) * GBS + bb];
            }

            float it = 1.f / (1.f + expf(-gi));
            float ft = 1.f / (1.f + expf(-gf));
            float ot = 1.f / (1.f + expf(-go));
            float ch = tanhf(gc);

            float cn = ft * cst + it * ch;
            float hn = ot * tanhf(cn);
            cst = cn;

            int ci = bb * HID + h;
            __nv_bfloat16 hhi = __float2bfloat16_rn(hn);
            g_h_hi[p ^ 1][ci] = hhi;
            g_h_lo[p ^ 1][ci] = __float2bfloat16_rn(hn - __bfloat162float(hhi));
            out[((size_t)bb * S_LEN + s) * HID + h] = hn;
            if (s == S_LEN - 1) g_c[ci] = cn;
        }

        // grid barrier (atomic monotonic counter — measured best)
        if (s < S_LEN - 1) {
            __syncthreads();
            if (t == 0) {
                __threadfence();
                unsigned my = atomicAdd(&g_bar_cnt, 1u) + 1u;
                unsigned need = ((my + NBLK - 1u) / NBLK) * NBLK;
                unsigned cur;
                do {
                    asm volatile("ld.acquire.gpu.u32 %0, [%1];" : "=r"(cur) : "l"(&g_bar_cnt));
                } while (cur < need);
            }
            __syncthreads();
        }
    }
}

// ---------------- finalize ----------------
__global__ void finalize_kernel(float* __restrict__ out) {
    int i = blockIdx.x * blockDim.x + threadIdx.x;
    if (i < BATCH * HID) {
        int b = i / HID, h = i % HID;
        const size_t OUT0 = (size_t)BATCH * S_LEN * HID;
        out[OUT0 + i]               = out[((size_t)b * S_LEN + (S_LEN - 1)) * HID + h];
        out[OUT0 + BATCH * HID + i] = g_c[i];
    }
}

// ---------------- launch ----------------
extern "C" void kernel_launch(void* const* d_in, const int* in_sizes, int n_in,
                              void* d_out, int out_size) {
    const float* inp  = (const float*)d_in[0];
    const float* Wx   = (const float*)d_in[1];
    const float* Wh   = (const float*)d_in[2];
    const float* bias = (const float*)d_in[3];
    float* out = (float*)d_out;

    void *p_in_hi, *p_in_lo, *p_wx_hi, *p_wx_lo, *p_wh_hi, *p_wh_lo;
    cudaGetSymbolAddress(&p_in_hi, g_in_hi);
    cudaGetSymbolAddress(&p_in_lo, g_in_lo);
    cudaGetSymbolAddress(&p_wx_hi, g_wx_hi);
    cudaGetSymbolAddress(&p_wx_lo, g_wx_lo);
    cudaGetSymbolAddress(&p_wh_hi, g_wh_hi);
    cudaGetSymbolAddress(&p_wh_lo, g_wh_lo);

    static int configured = 0;
    if (!configured) {
        cudaFuncSetAttribute(lstm_rec_kernel,
                             cudaFuncAttributeMaxDynamicSharedMemorySize, SMEM_REC);
        cudaFuncSetAttribute(xproj_kernel,
                             cudaFuncAttributeMaxDynamicSharedMemorySize, SMEM_XP);
        configured = 1;
    }

    const size_t n_inp = (size_t)BATCH * S_LEN * DIM;
    const size_t n_w   = (size_t)NG * DIM;

    split_kernel<<<(unsigned)((n_inp + 255) / 256), 256>>>(
        inp, (__nv_bfloat16*)p_in_hi, (__nv_bfloat16*)p_in_lo, n_inp);
    split_kernel<<<(unsigned)((n_w + 255) / 256), 256>>>(
        Wx, (__nv_bfloat16*)p_wx_hi, (__nv_bfloat16*)p_wx_lo, n_w);
    split_kernel<<<(unsigned)((n_w + 255) / 256), 256>>>(
        Wh, (__nv_bfloat16*)p_wh_hi, (__nv_bfloat16*)p_wh_lo, n_w);
    init_kernel<<<(BATCH * HID + 255) / 256, 256>>>();

    dim3 xg(NG / 128, S_LEN / 2);
    xproj_kernel<<<xg, 256, SMEM_XP>>>();

    lstm_rec_kernel<<<NBLK, 512, SMEM_REC>>>(bias, out);

    if ((size_t)out_size >= (size_t)BATCH * S_LEN * HID + 2 * BATCH * HID)
        finalize_kernel<<<(BATCH * HID + 255) / 256, 256>>>(out);
}